// round 6
// baseline (speedup 1.0000x reference)
#include <cuda_runtime.h>
#include <stdint.h>

#define BQ 4
#define LQ 2048
#define HQ 8
#define DQ 64
#define BH (BQ*HQ)      // 32
#define SK 40           // sample_k
#define NT 40           // n_top
#define NSEG 16
#define SEG 128         // NSEG*SEG == LQ
#define NPART 8
#define LPART (LQ/NPART) // 256
#define TL 64           // attn GEMM tile
#define NRANGE 8
#define RSIZE (LQ/NRANGE)   // 256 K-rows per range
#define KPAD 68             // padded row stride (floats) to spread smem banks
#define SMEM_M3 (RSIZE*KPAD*4)  // 69632 bytes

// ---------------- scratch (device globals; no allocation allowed) ----------
__device__ unsigned g_list[NRANGE*LQ*SK];     // per-(range,l) bucketed sample lists
__device__ int      g_cnt[NRANGE*LQ];
__device__ float    g_pmax[NRANGE*BH*LQ];
__device__ float    g_psum[NRANGE*BH*LQ];
__device__ float    g_M[BH*LQ];               // sparsity measure
__device__ int      g_top[BH*NT];             // top-n_top row indices
__device__ float    g_sinv[BH*NT];            // 1/sum(p)
__device__ float    g_scores[(size_t)BH*NT*LQ];  // unnormalized probs p (10.5MB)
__device__ float    g_seg[BH*NSEG*DQ];
__device__ float    g_off[BH*NSEG*DQ];
__device__ float    g_part[BH*NPART*NT*DQ];

// ---------------- Threefry-2x32 (JAX schedule) -----------------------------
__host__ __device__ static inline void tf2x32(unsigned k0, unsigned k1,
                                              unsigned x0, unsigned x1,
                                              unsigned* o0, unsigned* o1) {
    unsigned ks2 = k0 ^ k1 ^ 0x1BD11BDAu;
    unsigned v0 = x0 + k0, v1 = x1 + k1;
#define TFR(r) { v0 += v1; v1 = (v1<<(r))|(v1>>(32-(r))); v1 ^= v0; }
    TFR(13) TFR(15) TFR(26) TFR(6)
    v0 += k1;  v1 += ks2 + 1u;
    TFR(17) TFR(29) TFR(16) TFR(24)
    v0 += ks2; v1 += k0 + 2u;
    TFR(13) TFR(15) TFR(26) TFR(6)
    v0 += k0;  v1 += k1 + 3u;
    TFR(17) TFR(29) TFR(16) TFR(24)
    v0 += k1;  v1 += ks2 + 4u;
    TFR(13) TFR(15) TFR(26) TFR(6)
    v0 += ks2; v1 += k0 + 5u;
#undef TFR
    *o0 = v0; *o1 = v1;
}

// K0: threefry all 40 samples for row l, bucketed by key-range (deterministic order)
__global__ void k_sample(unsigned k2a, unsigned k2b) {
    int l = blockIdx.x*blockDim.x + threadIdx.x;
    if (l >= LQ) return;
    int cnt[NRANGE];
#pragma unroll
    for (int r = 0; r < NRANGE; r++) cnt[r] = 0;
    for (int s = 0; s < SK; s++) {
        unsigned o0, o1;
        tf2x32(k2a, k2b, 0u, (unsigned)(l*SK + s), &o0, &o1);
        unsigned r = (o0 ^ o1) & (LQ - 1);
        unsigned rg = r / RSIZE;
        g_list[((size_t)rg*LQ + l)*SK + cnt[rg]] = r;
        cnt[rg]++;
    }
#pragma unroll
    for (int r = 0; r < NRANGE; r++) g_cnt[r*LQ + l] = cnt[r];
}

// K1: per-(range,bh) partial max/sum of sampled dots; K chunk staged in smem.
__global__ void k_M3(const float* __restrict__ Q, const float* __restrict__ K) {
    extern __shared__ float sK[];   // [RSIZE][KPAD]
    int t = threadIdx.x;
    int range = blockIdx.x, bh = blockIdx.y;
    const float* Ksrc = K + ((size_t)bh*LQ + range*RSIZE)*DQ;
    for (int i = t; i < RSIZE*(DQ/4); i += 1024) {
        int row = i >> 4, c4 = i & 15;
        ((float4*)(sK + row*KPAD))[c4] = ((const float4*)(Ksrc + (size_t)row*DQ))[c4];
    }
    __syncthreads();
    int lane = t & 7, gid = t >> 3;            // 128 groups of 8 lanes
    for (int l = gid; l < LQ; l += 128) {
        int cnt = g_cnt[range*LQ + l];
        float mx = -3.402823466e38f, sm = 0.f;
        if (cnt) {
            const float4* q = (const float4*)(Q + ((size_t)bh*LQ + l)*DQ) + lane*2;
            float4 q0 = q[0], q1 = q[1];
            const unsigned* lst = g_list + ((size_t)range*LQ + l)*SK;
            for (int i = 0; i < cnt; i++) {
                int r = (int)lst[i] - range*RSIZE;
                const float* kr = sK + r*KPAD + lane*8;
                float4 k0 = *(const float4*)kr, k1 = *(const float4*)(kr+4);
                float d = q0.x*k0.x + q0.y*k0.y + q0.z*k0.z + q0.w*k0.w
                        + q1.x*k1.x + q1.y*k1.y + q1.z*k1.z + q1.w*k1.w;
                d += __shfl_xor_sync(0xffffffffu, d, 1);
                d += __shfl_xor_sync(0xffffffffu, d, 2);
                d += __shfl_xor_sync(0xffffffffu, d, 4);
                mx = fmaxf(mx, d);
                sm += d;
            }
        }
        if (lane == 0) {
            g_pmax[((size_t)range*BH + bh)*LQ + l] = mx;
            g_psum[((size_t)range*BH + bh)*LQ + l] = sm;
        }
    }
}

// K1b: combine range partials -> M
__global__ void k_Mcomb() {
    int i = blockIdx.x*blockDim.x + threadIdx.x;   // i = bh*LQ + l
    if (i >= BH*LQ) return;
    int bh = i >> 11, l = i & (LQ-1);
    float mx = -3.402823466e38f, sm = 0.f;
#pragma unroll
    for (int r = 0; r < NRANGE; r++) {
        mx = fmaxf(mx, g_pmax[((size_t)r*BH + bh)*LQ + l]);
        sm += g_psum[((size_t)r*BH + bh)*LQ + l];
    }
    g_M[i] = mx - sm * (1.f/2048.f);
}

// K2: exact top-40 via 1024-thread bitonic sort (value desc, index asc)
__global__ void k_topk() {
    __shared__ unsigned long long key[LQ];
    int t = threadIdx.x, bh = blockIdx.x;
    const float* Mr = g_M + bh*LQ;
#pragma unroll
    for (int i = t; i < LQ; i += 1024) {
        unsigned u = __float_as_uint(Mr[i]);
        u ^= (u >> 31) ? 0xFFFFFFFFu : 0x80000000u;     // order-preserving map
        key[i] = ((unsigned long long)(~u) << 32) | (unsigned)i;
    }
    __syncthreads();
    for (int k = 2; k <= LQ; k <<= 1) {
        for (int j = k >> 1; j > 0; j >>= 1) {
#pragma unroll
            for (int i = t; i < LQ; i += 1024) {
                int ixj = i ^ j;
                if (ixj > i) {
                    unsigned long long a = key[i], b = key[ixj];
                    bool up = ((i & k) == 0);
                    if ((a > b) == up) { key[i] = b; key[ixj] = a; }
                }
            }
            __syncthreads();
        }
    }
    if (t < NT) g_top[bh*NT + t] = (int)(key[t] & 0xFFFFFFFFu);
}

// K3: p[u,l] = masked? 0 : exp(0.0625*(Qsel[u]·K[l] + Q[l]·Ksel[u]))
// 20 u per block (blockIdx.y half), 2 l per thread.
__global__ void k_scores(const float* __restrict__ Q, const float* __restrict__ K) {
    __shared__ float4 qs[20][16];
    __shared__ float4 ks[20][16];
    __shared__ int pos[20];
    int t = threadIdx.x;
    int bh = blockIdx.z, uh = blockIdx.y;
    int l0 = blockIdx.x*512;
    const float* Qb = Q + (size_t)bh*LQ*DQ;
    const float* Kb = K + (size_t)bh*LQ*DQ;
    if (t < 20) pos[t] = g_top[bh*NT + uh*20 + t];
    __syncthreads();
    for (int e = t; e < 20*16; e += 256) {
        int u = e >> 4, c = e & 15;
        int p = pos[u];
        qs[u][c] = ((const float4*)(Qb + (size_t)p*DQ))[c];
        ks[u][c] = ((const float4*)(Kb + (size_t)p*DQ))[c];
    }
    __syncthreads();
    int la = l0 + t, lb = l0 + 256 + t;
    const float4* qra = (const float4*)(Qb + (size_t)la*DQ);
    const float4* kra = (const float4*)(Kb + (size_t)la*DQ);
    const float4* qrb = (const float4*)(Qb + (size_t)lb*DQ);
    const float4* krb = (const float4*)(Kb + (size_t)lb*DQ);
    float acca[20], accb[20];
#pragma unroll
    for (int u = 0; u < 20; u++) { acca[u] = 0.f; accb[u] = 0.f; }
#pragma unroll
    for (int c = 0; c < 16; c++) {
        float4 ka = kra[c], qa = qra[c];
        float4 kb = krb[c], qb = qrb[c];
#pragma unroll
        for (int u = 0; u < 20; u++) {
            float4 a = qs[u][c], b = ks[u][c];
            acca[u] += a.x*ka.x + a.y*ka.y + a.z*ka.z + a.w*ka.w
                     + b.x*qa.x + b.y*qa.y + b.z*qa.z + b.w*qa.w;
            accb[u] += a.x*kb.x + a.y*kb.y + a.z*kb.z + a.w*kb.w
                     + b.x*qb.x + b.y*qb.y + b.z*qb.z + b.w*qb.w;
        }
    }
    float* so = g_scores + (size_t)(bh*NT + uh*20)*LQ;
#pragma unroll
    for (int u = 0; u < 20; u++) {
        int p = pos[u];
        float pa = (la > p) ? 0.f : __expf(acca[u]*0.0625f);  // 0.5/sqrt(64)
        float pb = (lb > p) ? 0.f : __expf(accb[u]*0.0625f);
        so[(size_t)u*LQ + la] = pa;
        so[(size_t)u*LQ + lb] = pb;
    }
}

// K3b: row sums of p -> 1/sum
__global__ void k_sums() {
    int bh = blockIdx.x;
    int w = threadIdx.x >> 5, lane = threadIdx.x & 31;
    for (int u = w; u < NT; u += 8) {
        const float4* p = (const float4*)(g_scores + (size_t)(bh*NT + u)*LQ);
        float s = 0.f;
        for (int i = lane; i < LQ/4; i += 32) {
            float4 v = p[i];
            s += v.x + v.y + v.z + v.w;
        }
#pragma unroll
        for (int o = 16; o > 0; o >>= 1) s += __shfl_xor_sync(0xffffffffu, s, o);
        if (lane == 0) g_sinv[bh*NT + u] = 1.f / s;
    }
}

// K4: partial p@V per l-part (shared-tiled GEMM, unnormalized)
__global__ void k_attnpart(const float* __restrict__ V) {
    __shared__ float vt[TL][DQ];     // 16KB
    __shared__ float pt[NT][TL];     // 10KB
    int t = threadIdx.x;
    int bh = blockIdx.y, part = blockIdx.x;
    const float* Vb = V + (size_t)bh*LQ*DQ;
    int i = t >> 6;      // u-group 0..3
    int d = t & 63;
    float acc[10];
#pragma unroll
    for (int j = 0; j < 10; j++) acc[j] = 0.f;
    int l0 = part*LPART;
    for (int tile = 0; tile < LPART/TL; tile++) {
        int lb = l0 + tile*TL;
        __syncthreads();
        for (int e = t; e < TL*DQ/4; e += 256)
            ((float4*)&vt[0][0])[e] = ((const float4*)(Vb + (size_t)lb*DQ))[e];
        for (int e = t; e < NT*TL; e += 256) {
            int u = e / TL, ll = e % TL;
            pt[u][ll] = g_scores[(size_t)(bh*NT+u)*LQ + lb + ll];
        }
        __syncthreads();
#pragma unroll 1
        for (int ll = 0; ll < TL; ll += 4) {
            float v0 = vt[ll][d], v1 = vt[ll+1][d], v2 = vt[ll+2][d], v3 = vt[ll+3][d];
#pragma unroll
            for (int j = 0; j < 10; j++) {
                int u = i + 4*j;
                float4 p = *(const float4*)&pt[u][ll];
                acc[j] += p.x*v0 + p.y*v1 + p.z*v2 + p.w*v3;
            }
        }
    }
#pragma unroll
    for (int j = 0; j < 10; j++) {
        int u = i + 4*j;
        g_part[((size_t)(bh*NPART + part)*NT + u)*DQ + d] = acc[j];
    }
}

// C1: per-segment sums of V along L
__global__ void k_seg(const float* __restrict__ V) {
    int bh = blockIdx.y, seg = blockIdx.x, d = threadIdx.x;
    const float* Vb = V + ((size_t)bh*LQ + seg*SEG)*DQ + d;
    float a = 0.f;
#pragma unroll 8
    for (int i = 0; i < SEG; i++) a += Vb[(size_t)i*DQ];
    g_seg[(bh*NSEG + seg)*DQ + d] = a;
}

// C2: exclusive scan of segment sums
__global__ void k_segscan() {
    int bh = blockIdx.x, d = threadIdx.x;
    float off = 0.f;
#pragma unroll
    for (int s = 0; s < NSEG; s++) {
        g_off[(bh*NSEG + s)*DQ + d] = off;
        off += g_seg[(bh*NSEG + s)*DQ + d];
    }
}

// C3: context = 0.5*((l+1)*V + cumsum(V)); write full output (B,L,H,D)
__global__ void k_cumsum(const float* __restrict__ V, float* __restrict__ out) {
    int bh = blockIdx.y, seg = blockIdx.x, d = threadIdx.x;
    int b = bh >> 3, h = bh & 7;
    float run = g_off[(bh*NSEG + seg)*DQ + d];
    const float* Vb = V + ((size_t)bh*LQ + seg*SEG)*DQ + d;
    float* ob = out + (((size_t)b*LQ + seg*SEG)*HQ + h)*DQ + d;
#pragma unroll 8
    for (int i = 0; i < SEG; i++) {
        int l = seg*SEG + i;
        float v = Vb[(size_t)i*DQ];
        run += v;
        ob[(size_t)i*HQ*DQ] = 0.5f*((float)(l+1)*v + run);
    }
}

// K4c: combine partials, normalize, updated = 0.5*(V[pos] + attn@V), scatter
__global__ void k_scatter(const float* __restrict__ V, float* __restrict__ out) {
    int bh = blockIdx.x, t = threadIdx.x;
    int b = bh >> 3, h = bh & 7;
    for (int e = t; e < NT*DQ; e += 256) {
        int u = e >> 6, d = e & 63;
        int p = g_top[bh*NT + u];
        float sinv = g_sinv[bh*NT + u];
        float s = 0.f;
#pragma unroll
        for (int part = 0; part < NPART; part++)
            s += g_part[((size_t)(bh*NPART + part)*NT + u)*DQ + d];
        float vs = V[((size_t)bh*LQ + p)*DQ + d];
        out[(((size_t)b*LQ + p)*HQ + h)*DQ + d] = 0.5f*(vs + s*sinv);
    }
}

extern "C" void kernel_launch(void* const* d_in, const int* in_sizes, int n_in,
                              void* d_out, int out_size) {
    const float* Q = (const float*)d_in[0];
    const float* K = (const float*)d_in[1];
    const float* V = (const float*)d_in[2];
    float* out = (float*)d_out;

    // Enable >48KB dynamic smem for k_M3 (module-persistent; first call, pre-capture,
    // is the one that matters — ignore return value on captured calls).
    (void)cudaFuncSetAttribute(k_M3, cudaFuncAttributeMaxDynamicSharedMemorySize, SMEM_M3);

    // jax.random.split(key(42))[1] under the partitionable (foldlike) scheme:
    unsigned k2a, k2b;
    tf2x32(0u, 42u, 0u, 1u, &k2a, &k2b);

    k_sample<<<LQ/256, 256>>>(k2a, k2b);
    { dim3 g(NRANGE, BH); k_M3<<<g, 1024, SMEM_M3>>>(Q, K); }
    k_Mcomb<<<BH*LQ/1024, 1024>>>();
    k_topk<<<BH, 1024>>>();
    { dim3 g(LQ/512, 2, BH); k_scores<<<g, 256>>>(Q, K); }
    k_sums<<<BH, 256>>>();
    { dim3 g(NPART, BH); k_attnpart<<<g, 256>>>(V); }
    { dim3 g(NSEG, BH); k_seg<<<g, 64>>>(V); }
    k_segscan<<<BH, 64>>>();
    { dim3 g(NSEG, BH); k_cumsum<<<g, 64>>>(V, out); }
    k_scatter<<<BH, 256>>>(V, out);
}

// round 9
// speedup vs baseline: 3.5232x; 3.5232x over previous
#include <cuda_runtime.h>
#include <stdint.h>

#define BQ 4
#define LQ 2048
#define HQ 8
#define DQ 64
#define BH (BQ*HQ)      // 32
#define SK 40           // sample_k
#define NT 40           // n_top
#define NSEG 16
#define SEG 128         // NSEG*SEG == LQ
#define NPART 8
#define LPART (LQ/NPART) // 256
#define TL 64           // attn GEMM tile

// ---------------- scratch (device globals; no allocation allowed) ----------
__device__ unsigned g_idx[LQ*SK];             // sampled key indices (shared across b,h)
__device__ float    g_M[BH*LQ];               // sparsity measure
__device__ int      g_top[BH*NT];             // top-n_top row indices (any order)
__device__ float    g_sinv[BH*NT];            // 1/sum(p)
__device__ float    g_scores[(size_t)BH*NT*LQ];  // unnormalized probs p (10.5MB)
__device__ float    g_seg[BH*NSEG*DQ];
__device__ float    g_off[BH*NSEG*DQ];
__device__ float    g_part[BH*NPART*NT*DQ];

// ---------------- Threefry-2x32 (JAX schedule) -----------------------------
__host__ __device__ static inline void tf2x32(unsigned k0, unsigned k1,
                                              unsigned x0, unsigned x1,
                                              unsigned* o0, unsigned* o1) {
    unsigned ks2 = k0 ^ k1 ^ 0x1BD11BDAu;
    unsigned v0 = x0 + k0, v1 = x1 + k1;
#define TFR(r) { v0 += v1; v1 = (v1<<(r))|(v1>>(32-(r))); v1 ^= v0; }
    TFR(13) TFR(15) TFR(26) TFR(6)
    v0 += k1;  v1 += ks2 + 1u;
    TFR(17) TFR(29) TFR(16) TFR(24)
    v0 += ks2; v1 += k0 + 2u;
    TFR(13) TFR(15) TFR(26) TFR(6)
    v0 += k0;  v1 += k1 + 3u;
    TFR(17) TFR(29) TFR(16) TFR(24)
    v0 += k1;  v1 += ks2 + 4u;
    TFR(13) TFR(15) TFR(26) TFR(6)
    v0 += ks2; v1 += k0 + 5u;
#undef TFR
    *o0 = v0; *o1 = v1;
}

// K0: index_sample[i] = (o0^o1) & 2047, counter (0, i), key = k2
__global__ void k_sample(unsigned k2a, unsigned k2b) {
    int j = blockIdx.x*blockDim.x + threadIdx.x;
    if (j >= LQ*SK) return;
    unsigned o0, o1;
    tf2x32(k2a, k2b, 0u, (unsigned)j, &o0, &o1);
    g_idx[j] = (o0 ^ o1) & (LQ - 1);
}

// K1: M[bh,l] = max_s(Q[l]·K[idx[l,s]]) - sum_s(...)/L_K.  8 lanes per row.
__global__ void k_M(const float* __restrict__ Q, const float* __restrict__ K) {
    int t = threadIdx.x;
    int lane = t & 7;
    int row = blockIdx.x*32 + (t >> 3);   // bh*2048 + l
    int bh = row >> 11;
    int l  = row & (LQ - 1);
    const float4* q = (const float4*)(Q + (size_t)row*DQ) + lane*2;
    float4 q0 = q[0], q1 = q[1];
    float mx = -3.402823466e38f, sm = 0.f;
    const unsigned* idx = g_idx + l*SK;
    const float* Kb = K + (size_t)bh*LQ*DQ;
#pragma unroll 4
    for (int s = 0; s < SK; s++) {
        unsigned r = idx[s];
        const float4* kp = (const float4*)(Kb + (size_t)r*DQ) + lane*2;
        float4 k0 = kp[0], k1 = kp[1];
        float d = q0.x*k0.x + q0.y*k0.y + q0.z*k0.z + q0.w*k0.w
                + q1.x*k1.x + q1.y*k1.y + q1.z*k1.z + q1.w*k1.w;
        d += __shfl_xor_sync(0xffffffffu, d, 1);
        d += __shfl_xor_sync(0xffffffffu, d, 2);
        d += __shfl_xor_sync(0xffffffffu, d, 4);
        mx = fmaxf(mx, d);
        sm += d;
    }
    if (lane == 0) g_M[row] = mx - sm * (1.f/2048.f);
}

// K2: exact top-40 SET via 2-level radix select (no sort; downstream is
// order-invariant: each u's result lands at its own p = g_top[u]).
__global__ void k_topk() {
    __shared__ unsigned sval[LQ];               // 8KB order-mapped values
    __shared__ unsigned hist[256];
    __shared__ unsigned long long cand[LQ];     // 16KB candidate keys
    __shared__ int s_b1, s_c1, s_b2, s_c2, s_nc, s_nout;
    int t = threadIdx.x, bh = blockIdx.x;       // 256 threads
    const float* Mr = g_M + bh*LQ;
    for (int i = t; i < LQ; i += 256) {
        unsigned u = __float_as_uint(Mr[i]);
        u ^= (u >> 31) ? 0xFFFFFFFFu : 0x80000000u;   // ascending order map
        sval[i] = u;
    }
    hist[t] = 0;
    __syncthreads();
    for (int i = t; i < LQ; i += 256) atomicAdd(&hist[sval[i] >> 24], 1u);
    __syncthreads();
    if (t == 0) {
        int cum = 0, b = 255;
        for (; b > 0; b--) { if (cum + (int)hist[b] >= NT) break; cum += (int)hist[b]; }
        s_b1 = b; s_c1 = cum;
    }
    __syncthreads();
    int b1 = s_b1, c1 = s_c1;
    hist[t] = 0;
    __syncthreads();
    for (int i = t; i < LQ; i += 256) {
        unsigned v = sval[i];
        if ((int)(v >> 24) == b1) atomicAdd(&hist[(v >> 16) & 255u], 1u);
    }
    __syncthreads();
    if (t == 0) {
        int need = NT - c1;
        int cum = 0, b = 255;
        for (; b > 0; b--) { if (cum + (int)hist[b] >= need) break; cum += (int)hist[b]; }
        s_b2 = b; s_c2 = cum; s_nc = 0; s_nout = 0;
    }
    __syncthreads();
    int b2 = s_b2;
    int r = NT - c1 - s_c2;            // winners still needed from candidate bin
    for (int i = t; i < LQ; i += 256) {
        unsigned v = sval[i];
        int hb = (int)(v >> 24), mb = (int)((v >> 16) & 255u);
        if (hb > b1 || (hb == b1 && mb > b2)) {
            int slot = atomicAdd(&s_nout, 1);
            g_top[bh*NT + slot] = i;
        } else if (hb == b1 && mb == b2) {
            int slot = atomicAdd(&s_nc, 1);
            // bigger key = better; tie-break smaller index wins via (LQ-1-i)
            cand[slot] = ((unsigned long long)v << 32) | (unsigned)(LQ - 1 - i);
        }
    }
    __syncthreads();
    int nc = s_nc;
    for (int c = t; c < nc; c += 256) {
        unsigned long long k = cand[c];
        int rank = 0;
        for (int j = 0; j < nc; j++) rank += (cand[j] > k);
        if (rank < r) {
            int slot = atomicAdd(&s_nout, 1);
            g_top[bh*NT + slot] = LQ - 1 - (int)(k & 0xFFFFFFFFu);
        }
    }
}

// K3: p[u,l] = masked? 0 : exp(0.0625*(Qsel[u]·K[l] + Q[l]·Ksel[u]))
// 20 u per block (blockIdx.y half), 2 l per thread.
__global__ void k_scores(const float* __restrict__ Q, const float* __restrict__ K) {
    __shared__ float4 qs[20][16];
    __shared__ float4 ks[20][16];
    __shared__ int pos[20];
    int t = threadIdx.x;
    int bh = blockIdx.z, uh = blockIdx.y;
    int l0 = blockIdx.x*512;
    const float* Qb = Q + (size_t)bh*LQ*DQ;
    const float* Kb = K + (size_t)bh*LQ*DQ;
    if (t < 20) pos[t] = g_top[bh*NT + uh*20 + t];
    __syncthreads();
    for (int e = t; e < 20*16; e += 256) {
        int u = e >> 4, c = e & 15;
        int p = pos[u];
        qs[u][c] = ((const float4*)(Qb + (size_t)p*DQ))[c];
        ks[u][c] = ((const float4*)(Kb + (size_t)p*DQ))[c];
    }
    __syncthreads();
    int la = l0 + t, lb = l0 + 256 + t;
    const float4* qra = (const float4*)(Qb + (size_t)la*DQ);
    const float4* kra = (const float4*)(Kb + (size_t)la*DQ);
    const float4* qrb = (const float4*)(Qb + (size_t)lb*DQ);
    const float4* krb = (const float4*)(Kb + (size_t)lb*DQ);
    float acca[20], accb[20];
#pragma unroll
    for (int u = 0; u < 20; u++) { acca[u] = 0.f; accb[u] = 0.f; }
#pragma unroll
    for (int c = 0; c < 16; c++) {
        float4 ka = kra[c], qa = qra[c];
        float4 kb = krb[c], qb = qrb[c];
#pragma unroll
        for (int u = 0; u < 20; u++) {
            float4 a = qs[u][c], b = ks[u][c];
            acca[u] += a.x*ka.x + a.y*ka.y + a.z*ka.z + a.w*ka.w
                     + b.x*qa.x + b.y*qa.y + b.z*qa.z + b.w*qa.w;
            accb[u] += a.x*kb.x + a.y*kb.y + a.z*kb.z + a.w*kb.w
                     + b.x*qb.x + b.y*qb.y + b.z*qb.z + b.w*qb.w;
        }
    }
    float* so = g_scores + (size_t)(bh*NT + uh*20)*LQ;
#pragma unroll
    for (int u = 0; u < 20; u++) {
        int p = pos[u];
        float pa = (la > p) ? 0.f : __expf(acca[u]*0.0625f);  // 0.5/sqrt(64)
        float pb = (lb > p) ? 0.f : __expf(accb[u]*0.0625f);
        so[(size_t)u*LQ + la] = pa;
        so[(size_t)u*LQ + lb] = pb;
    }
}

// K3b: row sums of p -> 1/sum
__global__ void k_sums() {
    int bh = blockIdx.x;
    int w = threadIdx.x >> 5, lane = threadIdx.x & 31;
    for (int u = w; u < NT; u += 8) {
        const float4* p = (const float4*)(g_scores + (size_t)(bh*NT + u)*LQ);
        float s = 0.f;
        for (int i = lane; i < LQ/4; i += 32) {
            float4 v = p[i];
            s += v.x + v.y + v.z + v.w;
        }
#pragma unroll
        for (int o = 16; o > 0; o >>= 1) s += __shfl_xor_sync(0xffffffffu, s, o);
        if (lane == 0) g_sinv[bh*NT + u] = 1.f / s;
    }
}

// K4: partial p@V per l-part (shared-tiled GEMM, unnormalized)
__global__ void k_attnpart(const float* __restrict__ V) {
    __shared__ float vt[TL][DQ];     // 16KB
    __shared__ float pt[NT][TL];     // 10KB
    int t = threadIdx.x;
    int bh = blockIdx.y, part = blockIdx.x;
    const float* Vb = V + (size_t)bh*LQ*DQ;
    int i = t >> 6;      // u-group 0..3
    int d = t & 63;
    float acc[10];
#pragma unroll
    for (int j = 0; j < 10; j++) acc[j] = 0.f;
    int l0 = part*LPART;
    for (int tile = 0; tile < LPART/TL; tile++) {
        int lb = l0 + tile*TL;
        __syncthreads();
        for (int e = t; e < TL*DQ/4; e += 256)
            ((float4*)&vt[0][0])[e] = ((const float4*)(Vb + (size_t)lb*DQ))[e];
        for (int e = t; e < NT*TL; e += 256) {
            int u = e / TL, ll = e % TL;
            pt[u][ll] = g_scores[(size_t)(bh*NT+u)*LQ + lb + ll];
        }
        __syncthreads();
#pragma unroll 1
        for (int ll = 0; ll < TL; ll += 4) {
            float v0 = vt[ll][d], v1 = vt[ll+1][d], v2 = vt[ll+2][d], v3 = vt[ll+3][d];
#pragma unroll
            for (int j = 0; j < 10; j++) {
                int u = i + 4*j;
                float4 p = *(const float4*)&pt[u][ll];
                acc[j] += p.x*v0 + p.y*v1 + p.z*v2 + p.w*v3;
            }
        }
    }
#pragma unroll
    for (int j = 0; j < 10; j++) {
        int u = i + 4*j;
        g_part[((size_t)(bh*NPART + part)*NT + u)*DQ + d] = acc[j];
    }
}

// C1: per-segment sums of V along L
__global__ void k_seg(const float* __restrict__ V) {
    int bh = blockIdx.y, seg = blockIdx.x, d = threadIdx.x;
    const float* Vb = V + ((size_t)bh*LQ + seg*SEG)*DQ + d;
    float a = 0.f;
#pragma unroll 8
    for (int i = 0; i < SEG; i++) a += Vb[(size_t)i*DQ];
    g_seg[(bh*NSEG + seg)*DQ + d] = a;
}

// C2: exclusive scan of segment sums
__global__ void k_segscan() {
    int bh = blockIdx.x, d = threadIdx.x;
    float off = 0.f;
#pragma unroll
    for (int s = 0; s < NSEG; s++) {
        g_off[(bh*NSEG + s)*DQ + d] = off;
        off += g_seg[(bh*NSEG + s)*DQ + d];
    }
}

// C3: context = 0.5*((l+1)*V + cumsum(V)); write full output (B,L,H,D)
__global__ void k_cumsum(const float* __restrict__ V, float* __restrict__ out) {
    int bh = blockIdx.y, seg = blockIdx.x, d = threadIdx.x;
    int b = bh >> 3, h = bh & 7;
    float run = g_off[(bh*NSEG + seg)*DQ + d];
    const float* Vb = V + ((size_t)bh*LQ + seg*SEG)*DQ + d;
    float* ob = out + (((size_t)b*LQ + seg*SEG)*HQ + h)*DQ + d;
#pragma unroll 8
    for (int i = 0; i < SEG; i++) {
        int l = seg*SEG + i;
        float v = Vb[(size_t)i*DQ];
        run += v;
        ob[(size_t)i*HQ*DQ] = 0.5f*((float)(l+1)*v + run);
    }
}

// K4c: combine partials, normalize, updated = 0.5*(V[pos] + attn@V), scatter
__global__ void k_scatter(const float* __restrict__ V, float* __restrict__ out) {
    int bh = blockIdx.x, t = threadIdx.x;
    int b = bh >> 3, h = bh & 7;
    for (int e = t; e < NT*DQ; e += 256) {
        int u = e >> 6, d = e & 63;
        int p = g_top[bh*NT + u];
        float sinv = g_sinv[bh*NT + u];
        float s = 0.f;
#pragma unroll
        for (int part = 0; part < NPART; part++)
            s += g_part[((size_t)(bh*NPART + part)*NT + u)*DQ + d];
        float vs = V[((size_t)bh*LQ + p)*DQ + d];
        out[(((size_t)b*LQ + p)*HQ + h)*DQ + d] = 0.5f*(vs + s*sinv);
    }
}

extern "C" void kernel_launch(void* const* d_in, const int* in_sizes, int n_in,
                              void* d_out, int out_size) {
    const float* Q = (const float*)d_in[0];
    const float* K = (const float*)d_in[1];
    const float* V = (const float*)d_in[2];
    float* out = (float*)d_out;

    // jax.random.split(key(42))[1] under the partitionable (foldlike) scheme:
    unsigned k2a, k2b;
    tf2x32(0u, 42u, 0u, 1u, &k2a, &k2b);

    k_sample<<<(LQ*SK + 255)/256, 256>>>(k2a, k2b);
    k_M<<<(BH*LQ)/32, 256>>>(Q, K);
    k_topk<<<BH, 256>>>();
    { dim3 g(LQ/512, 2, BH); k_scores<<<g, 256>>>(Q, K); }
    k_sums<<<BH, 256>>>();
    { dim3 g(NPART, BH); k_attnpart<<<g, 256>>>(V); }
    { dim3 g(NSEG, BH); k_seg<<<g, 64>>>(V); }
    k_segscan<<<BH, 64>>>();
    { dim3 g(NSEG, BH); k_cumsum<<<g, 64>>>(V, out); }
    k_scatter<<<BH, 256>>>(V, out);
}

// round 11
// speedup vs baseline: 3.6686x; 1.0412x over previous
#include <cuda_runtime.h>
#include <stdint.h>

#define BQ 4
#define LQ 2048
#define HQ 8
#define DQ 64
#define BH (BQ*HQ)      // 32
#define SK 40           // sample_k
#define NT 40           // n_top
#define NSEG 16
#define SEG 128         // NSEG*SEG == LQ
#define NLG 4           // l-groups of 512 for fused kernel
#define LG  (LQ/NLG)    // 512

// ---------------- scratch (device globals; no allocation allowed) ----------
__device__ unsigned g_idx[LQ*SK];             // sampled key indices (shared across b,h)
__device__ float    g_M[BH*LQ];               // sparsity measure
__device__ int      g_top[BH*NT];             // top-n_top row indices (any order)
__device__ float    g_sums4[BH*2*NLG*20];     // per-(bh,uhalf,lgroup) partial row sums
__device__ float    g_part[(size_t)BH*2*NLG*20*DQ];  // partial p@V
__device__ float    g_seg[BH*NSEG*DQ];
__device__ float    g_off[BH*NSEG*DQ];

// ---------------- Threefry-2x32 (JAX schedule) -----------------------------
__host__ __device__ static inline void tf2x32(unsigned k0, unsigned k1,
                                              unsigned x0, unsigned x1,
                                              unsigned* o0, unsigned* o1) {
    unsigned ks2 = k0 ^ k1 ^ 0x1BD11BDAu;
    unsigned v0 = x0 + k0, v1 = x1 + k1;
#define TFR(r) { v0 += v1; v1 = (v1<<(r))|(v1>>(32-(r))); v1 ^= v0; }
    TFR(13) TFR(15) TFR(26) TFR(6)
    v0 += k1;  v1 += ks2 + 1u;
    TFR(17) TFR(29) TFR(16) TFR(24)
    v0 += ks2; v1 += k0 + 2u;
    TFR(13) TFR(15) TFR(26) TFR(6)
    v0 += k0;  v1 += k1 + 3u;
    TFR(17) TFR(29) TFR(16) TFR(24)
    v0 += k1;  v1 += ks2 + 4u;
    TFR(13) TFR(15) TFR(26) TFR(6)
    v0 += ks2; v1 += k0 + 5u;
#undef TFR
    *o0 = v0; *o1 = v1;
}

// K0: index_sample[i] = (o0^o1) & 2047, counter (0, i), key = k2
__global__ void k_sample(unsigned k2a, unsigned k2b) {
    int j = blockIdx.x*blockDim.x + threadIdx.x;
    if (j >= LQ*SK) return;
    unsigned o0, o1;
    tf2x32(k2a, k2b, 0u, (unsigned)j, &o0, &o1);
    g_idx[j] = (o0 ^ o1) & (LQ - 1);
}

// K1: M[bh,l] = max_s(Q[l]·K[idx[l,s]]) - sum_s(...)/L_K.  8 lanes per row.
__global__ void k_M(const float* __restrict__ Q, const float* __restrict__ K) {
    int t = threadIdx.x;
    int lane = t & 7;
    int row = blockIdx.x*32 + (t >> 3);   // bh*2048 + l
    int bh = row >> 11;
    int l  = row & (LQ - 1);
    const float4* q = (const float4*)(Q + (size_t)row*DQ) + lane*2;
    float4 q0 = q[0], q1 = q[1];
    float mx = -3.402823466e38f, sm = 0.f;
    const unsigned* idx = g_idx + l*SK;
    const float* Kb = K + (size_t)bh*LQ*DQ;
#pragma unroll 4
    for (int s = 0; s < SK; s++) {
        unsigned r = idx[s];
        const float4* kp = (const float4*)(Kb + (size_t)r*DQ) + lane*2;
        float4 k0 = kp[0], k1 = kp[1];
        float d = q0.x*k0.x + q0.y*k0.y + q0.z*k0.z + q0.w*k0.w
                + q1.x*k1.x + q1.y*k1.y + q1.z*k1.z + q1.w*k1.w;
        d += __shfl_xor_sync(0xffffffffu, d, 1);
        d += __shfl_xor_sync(0xffffffffu, d, 2);
        d += __shfl_xor_sync(0xffffffffu, d, 4);
        mx = fmaxf(mx, d);
        sm += d;
    }
    if (lane == 0) g_M[row] = mx - sm * (1.f/2048.f);
}

// K2: exact top-40 SET via 2-level radix select (order-invariant downstream)
__global__ void k_topk() {
    __shared__ unsigned sval[LQ];
    __shared__ unsigned hist[256];
    __shared__ unsigned long long cand[LQ];
    __shared__ int s_b1, s_c1, s_b2, s_c2, s_nc, s_nout;
    int t = threadIdx.x, bh = blockIdx.x;
    const float* Mr = g_M + bh*LQ;
    for (int i = t; i < LQ; i += 256) {
        unsigned u = __float_as_uint(Mr[i]);
        u ^= (u >> 31) ? 0xFFFFFFFFu : 0x80000000u;
        sval[i] = u;
    }
    hist[t] = 0;
    __syncthreads();
    for (int i = t; i < LQ; i += 256) atomicAdd(&hist[sval[i] >> 24], 1u);
    __syncthreads();
    if (t == 0) {
        int cum = 0, b = 255;
        for (; b > 0; b--) { if (cum + (int)hist[b] >= NT) break; cum += (int)hist[b]; }
        s_b1 = b; s_c1 = cum;
    }
    __syncthreads();
    int b1 = s_b1, c1 = s_c1;
    hist[t] = 0;
    __syncthreads();
    for (int i = t; i < LQ; i += 256) {
        unsigned v = sval[i];
        if ((int)(v >> 24) == b1) atomicAdd(&hist[(v >> 16) & 255u], 1u);
    }
    __syncthreads();
    if (t == 0) {
        int need = NT - c1;
        int cum = 0, b = 255;
        for (; b > 0; b--) { if (cum + (int)hist[b] >= need) break; cum += (int)hist[b]; }
        s_b2 = b; s_c2 = cum; s_nc = 0; s_nout = 0;
    }
    __syncthreads();
    int b2 = s_b2;
    int r = NT - c1 - s_c2;
    for (int i = t; i < LQ; i += 256) {
        unsigned v = sval[i];
        int hb = (int)(v >> 24), mb = (int)((v >> 16) & 255u);
        if (hb > b1 || (hb == b1 && mb > b2)) {
            int slot = atomicAdd(&s_nout, 1);
            g_top[bh*NT + slot] = i;
        } else if (hb == b1 && mb == b2) {
            int slot = atomicAdd(&s_nc, 1);
            cand[slot] = ((unsigned long long)v << 32) | (unsigned)(LQ - 1 - i);
        }
    }
    __syncthreads();
    int nc = s_nc;
    for (int c = t; c < nc; c += 256) {
        unsigned long long k = cand[c];
        int rank = 0;
        for (int j = 0; j < nc; j++) rank += (cand[j] > k);
        if (rank < r) {
            int slot = atomicAdd(&s_nout, 1);
            g_top[bh*NT + slot] = LQ - 1 - (int)(k & 0xFFFFFFFFu);
        }
    }
}

// FUSED: scores (20u x 512l chunk into smem) + row-sum partials + p@V partials.
// grid (NLG, 2, BH), 256 threads, 57344B dynamic smem.
// smem layout: pt[20*512] (40KB) | buf[4096] (16KB: qs/ks in phase A, vt in phase C)
__global__ void k_fused(const float* __restrict__ Q, const float* __restrict__ K,
                        const float* __restrict__ V) {
    extern __shared__ float smem[];
    float* pt  = smem;             // [20][512]
    float* buf = smem + 20*LG;     // 4096 floats
    __shared__ int pos[20];
    int t = threadIdx.x;
    int lg = blockIdx.x, uh = blockIdx.y, bh = blockIdx.z;
    const float* Qb = Q + (size_t)bh*LQ*DQ;
    const float* Kb = K + (size_t)bh*LQ*DQ;
    if (t < 20) pos[t] = g_top[bh*NT + uh*20 + t];
    __syncthreads();

    // ---- Phase A: scores -> pt ----
    float4* qs4 = (float4*)buf;        // [20][16]
    float4* ks4 = qs4 + 320;           // [20][16]
    for (int e = t; e < 320; e += 256) {
        int u = e >> 4, c = e & 15;
        int p = pos[u];
        qs4[e] = ((const float4*)(Qb + (size_t)p*DQ))[c];
        ks4[e] = ((const float4*)(Kb + (size_t)p*DQ))[c];
    }
    __syncthreads();
    int l0 = lg*LG;
    int la = l0 + t, lb = l0 + 256 + t;
    const float4* qra = (const float4*)(Qb + (size_t)la*DQ);
    const float4* kra = (const float4*)(Kb + (size_t)la*DQ);
    const float4* qrb = (const float4*)(Qb + (size_t)lb*DQ);
    const float4* krb = (const float4*)(Kb + (size_t)lb*DQ);
    float acca[20], accb[20];
#pragma unroll
    for (int u = 0; u < 20; u++) { acca[u] = 0.f; accb[u] = 0.f; }
#pragma unroll
    for (int c = 0; c < 16; c++) {
        float4 ka = kra[c], qa = qra[c];
        float4 kb = krb[c], qb = qrb[c];
#pragma unroll
        for (int u = 0; u < 20; u++) {
            float4 a = qs4[u*16 + c], b = ks4[u*16 + c];
            acca[u] += a.x*ka.x + a.y*ka.y + a.z*ka.z + a.w*ka.w
                     + b.x*qa.x + b.y*qa.y + b.z*qa.z + b.w*qa.w;
            accb[u] += a.x*kb.x + a.y*kb.y + a.z*kb.z + a.w*kb.w
                     + b.x*qb.x + b.y*qb.y + b.z*qb.z + b.w*qb.w;
        }
    }
#pragma unroll
    for (int u = 0; u < 20; u++) {
        int p = pos[u];
        pt[u*LG + t]       = (la > p) ? 0.f : __expf(acca[u]*0.0625f);
        pt[u*LG + 256 + t] = (lb > p) ? 0.f : __expf(accb[u]*0.0625f);
    }
    __syncthreads();

    // ---- Phase B: partial row sums ----
    {
        int w = t >> 5, lane = t & 31;
        for (int u = w; u < 20; u += 8) {
            const float4* pr = (const float4*)(pt + u*LG);
            float s = 0.f;
            for (int i = lane; i < LG/4; i += 32) {
                float4 v = pr[i];
                s += v.x + v.y + v.z + v.w;
            }
#pragma unroll
            for (int o = 16; o > 0; o >>= 1) s += __shfl_xor_sync(0xffffffffu, s, o);
            if (lane == 0) g_sums4[((bh*2 + uh)*NLG + lg)*20 + u] = s;
        }
    }

    // ---- Phase C: pt @ V-chunk -> g_part ----
    float* vt = buf;                  // [64][64], overwrites qs/ks (dead)
    int i = t >> 6, d = t & 63;
    float acc[5];
#pragma unroll
    for (int j = 0; j < 5; j++) acc[j] = 0.f;
    const float* Vb = V + ((size_t)bh*LQ + l0)*DQ;
    for (int tile = 0; tile < LG/64; tile++) {
        __syncthreads();
        for (int e = t; e < 64*DQ/4; e += 256)
            ((float4*)vt)[e] = ((const float4*)(Vb + (size_t)tile*64*DQ))[e];
        __syncthreads();
#pragma unroll 1
        for (int ll = 0; ll < 64; ll += 4) {
            float v0 = vt[ll*DQ + d],     v1 = vt[(ll+1)*DQ + d];
            float v2 = vt[(ll+2)*DQ + d], v3 = vt[(ll+3)*DQ + d];
#pragma unroll
            for (int j = 0; j < 5; j++) {
                int u = i + 4*j;
                float4 p = *(const float4*)(pt + u*LG + tile*64 + ll);
                acc[j] += p.x*v0 + p.y*v1 + p.z*v2 + p.w*v3;
            }
        }
    }
#pragma unroll
    for (int j = 0; j < 5; j++) {
        int u = i + 4*j;
        g_part[(((size_t)(bh*2 + uh)*NLG + lg)*20 + u)*DQ + d] = acc[j];
    }
}

// C1: per-segment sums of V along L
__global__ void k_seg(const float* __restrict__ V) {
    int bh = blockIdx.y, seg = blockIdx.x, d = threadIdx.x;
    const float* Vb = V + ((size_t)bh*LQ + seg*SEG)*DQ + d;
    float a = 0.f;
#pragma unroll 8
    for (int i = 0; i < SEG; i++) a += Vb[(size_t)i*DQ];
    g_seg[(bh*NSEG + seg)*DQ + d] = a;
}

// C2: exclusive scan of segment sums
__global__ void k_segscan() {
    int bh = blockIdx.x, d = threadIdx.x;
    float off = 0.f;
#pragma unroll
    for (int s = 0; s < NSEG; s++) {
        g_off[(bh*NSEG + s)*DQ + d] = off;
        off += g_seg[(bh*NSEG + s)*DQ + d];
    }
}

// C3: context = 0.5*((l+1)*V + cumsum(V)); write full output (B,L,H,D)
__global__ void k_cumsum(const float* __restrict__ V, float* __restrict__ out) {
    int bh = blockIdx.y, seg = blockIdx.x, d = threadIdx.x;
    int b = bh >> 3, h = bh & 7;
    float run = g_off[(bh*NSEG + seg)*DQ + d];
    const float* Vb = V + ((size_t)bh*LQ + seg*SEG)*DQ + d;
    float* ob = out + (((size_t)b*LQ + seg*SEG)*HQ + h)*DQ + d;
#pragma unroll 8
    for (int i = 0; i < SEG; i++) {
        int l = seg*SEG + i;
        float v = Vb[(size_t)i*DQ];
        run += v;
        ob[(size_t)i*HQ*DQ] = 0.5f*((float)(l+1)*v + run);
    }
}

// K4c: combine partials, normalize, updated = 0.5*(V[pos] + attn@V), scatter
__global__ void k_scatter(const float* __restrict__ V, float* __restrict__ out) {
    int bh = blockIdx.x, t = threadIdx.x;
    int b = bh >> 3, h = bh & 7;
    for (int e = t; e < NT*DQ; e += 256) {
        int g = e >> 6, d = e & 63;
        int uh = g / 20, ur = g % 20;
        int p = g_top[bh*NT + g];
        float s = 0.f, ssum = 0.f;
#pragma unroll
        for (int lg = 0; lg < NLG; lg++) {
            s    += g_part[(((size_t)(bh*2 + uh)*NLG + lg)*20 + ur)*DQ + d];
            ssum += g_sums4[((bh*2 + uh)*NLG + lg)*20 + ur];
        }
        float vs = V[((size_t)bh*LQ + p)*DQ + d];
        out[(((size_t)b*LQ + p)*HQ + h)*DQ + d] = 0.5f*(vs + s/ssum);
    }
}

extern "C" void kernel_launch(void* const* d_in, const int* in_sizes, int n_in,
                              void* d_out, int out_size) {
    const float* Q = (const float*)d_in[0];
    const float* K = (const float*)d_in[1];
    const float* V = (const float*)d_in[2];
    float* out = (float*)d_out;

    const int FUSED_SMEM = (20*LG + 64*DQ) * 4;   // 57344 bytes
    (void)cudaFuncSetAttribute(k_fused, cudaFuncAttributeMaxDynamicSharedMemorySize,
                               FUSED_SMEM);

    // jax.random.split(key(42))[1] under the partitionable (foldlike) scheme:
    unsigned k2a, k2b;
    tf2x32(0u, 42u, 0u, 1u, &k2a, &k2b);

    k_sample<<<(LQ*SK + 255)/256, 256>>>(k2a, k2b);
    k_M<<<(BH*LQ)/32, 256>>>(Q, K);
    k_topk<<<BH, 256>>>();
    { dim3 g(NLG, 2, BH); k_fused<<<g, 256, FUSED_SMEM>>>(Q, K, V); }
    { dim3 g(NSEG, BH); k_seg<<<g, 64>>>(V); }
    k_segscan<<<BH, 64>>>();
    { dim3 g(NSEG, BH); k_cumsum<<<g, 64>>>(V, out); }
    k_scatter<<<BH, 256>>>(V, out);
}